// round 1
// baseline (speedup 1.0000x reference)
#include <cuda_runtime.h>

#define BB 128
#define NN 512
#define FF 5
#define HH 64
#define KK 16

// Scratch (device globals: allocation-free)
__device__ float g_hA[BB * NN * HH];   // 16 MB
__device__ float g_hB[BB * NN * HH];   // 16 MB
__device__ int   g_idx[BB * NN * KK];  // 4 MB

__device__ __forceinline__ float elu_f(float x) {
    return x > 0.f ? x : (__expf(x) - 1.f);
}

// ---------------------------------------------------------------------------
// Input MLP: x[B,N,5] -> h[B,N,64], three elu layers.
// CTA: 256 threads = 16 nodes x 16 feature-quads (float4 per thread).
// ---------------------------------------------------------------------------
__global__ __launch_bounds__(256) void input_kernel(
    const float* __restrict__ x,
    const float* __restrict__ W0, const float* __restrict__ b0,
    const float* __restrict__ W1, const float* __restrict__ b1,
    const float* __restrict__ W2, const float* __restrict__ b2,
    float* __restrict__ out)
{
    __shared__ float sW0[FF * HH];
    __shared__ float sW1[HH * HH];
    __shared__ float sW2[HH * HH];
    __shared__ float sx[16][FF];
    __shared__ float sh[16][HH];

    int tid = threadIdx.x;
    for (int t = tid; t < FF * HH; t += 256) sW0[t] = W0[t];
    for (int t = tid; t < HH * HH; t += 256) { sW1[t] = W1[t]; sW2[t] = W2[t]; }

    int node0 = blockIdx.x * 16;
    if (tid < 16 * FF) sx[tid / FF][tid % FF] = x[(size_t)(node0 + tid / FF) * FF + tid % FF];
    __syncthreads();

    int nl = tid >> 4, tn = tid & 15;

    // layer 1 (K=5)
    float4 acc = *(const float4*)(b0 + tn * 4);
    #pragma unroll
    for (int d = 0; d < FF; d++) {
        float v = sx[nl][d];
        float4 w = *(const float4*)(sW0 + d * HH + tn * 4);
        acc.x = fmaf(v, w.x, acc.x); acc.y = fmaf(v, w.y, acc.y);
        acc.z = fmaf(v, w.z, acc.z); acc.w = fmaf(v, w.w, acc.w);
    }
    acc.x = elu_f(acc.x); acc.y = elu_f(acc.y); acc.z = elu_f(acc.z); acc.w = elu_f(acc.w);
    ((float4*)(sh[nl]))[tn] = acc;
    __syncthreads();

    // layer 2
    float4 a2 = *(const float4*)(b1 + tn * 4);
    #pragma unroll 8
    for (int d = 0; d < HH; d++) {
        float v = sh[nl][d];
        float4 w = *(const float4*)(sW1 + d * HH + tn * 4);
        a2.x = fmaf(v, w.x, a2.x); a2.y = fmaf(v, w.y, a2.y);
        a2.z = fmaf(v, w.z, a2.z); a2.w = fmaf(v, w.w, a2.w);
    }
    __syncthreads();   // everyone done reading sh before overwrite
    a2.x = elu_f(a2.x); a2.y = elu_f(a2.y); a2.z = elu_f(a2.z); a2.w = elu_f(a2.w);
    ((float4*)(sh[nl]))[tn] = a2;
    __syncthreads();

    // layer 3 -> global
    float4 a3 = *(const float4*)(b2 + tn * 4);
    #pragma unroll 8
    for (int d = 0; d < HH; d++) {
        float v = sh[nl][d];
        float4 w = *(const float4*)(sW2 + d * HH + tn * 4);
        a3.x = fmaf(v, w.x, a3.x); a3.y = fmaf(v, w.y, a3.y);
        a3.z = fmaf(v, w.z, a3.z); a3.w = fmaf(v, w.w, a3.w);
    }
    a3.x = elu_f(a3.x); a3.y = elu_f(a3.y); a3.z = elu_f(a3.z); a3.w = elu_f(a3.w);
    *(float4*)(out + (size_t)(node0 + nl) * HH + tn * 4) = a3;
}

// ---------------------------------------------------------------------------
// kNN: one CTA per graph. h_b (512x64 fp32 = 128 KB) in dynamic smem.
// Thread i owns node i: row cached in 64 regs, j-loop is broadcast LDS.128 +
// FFMA (FMA-bound). Top-16 via predicate-unrolled replace (strict '<' keeps
// earliest index == jax.lax.top_k tie behavior).
// ---------------------------------------------------------------------------
#define KNN_SMEM ((NN * HH + NN) * 4)

__global__ __launch_bounds__(512, 1) void knn_kernel(
    const float* __restrict__ h, int* __restrict__ nbr)
{
    extern __shared__ float sm[];
    float* sq = sm + NN * HH;
    int b = blockIdx.x, i = threadIdx.x;

    const float4* src4 = (const float4*)(h + (size_t)b * NN * HH);
    float4* dst4 = (float4*)sm;
    for (int t = i; t < NN * HH / 4; t += NN) dst4[t] = src4[t];
    __syncthreads();

    float r[HH];
    #pragma unroll
    for (int q = 0; q < HH / 4; q++) {
        float4 v = ((const float4*)(sm + i * HH))[q];
        r[4 * q] = v.x; r[4 * q + 1] = v.y; r[4 * q + 2] = v.z; r[4 * q + 3] = v.w;
    }
    float s = 0.f;
    #pragma unroll
    for (int d = 0; d < HH; d++) s = fmaf(r[d], r[d], s);
    sq[i] = s;
    __syncthreads();

    float bd[KK]; int bi[KK];
    #pragma unroll
    for (int t = 0; t < KK; t++) { bd[t] = 1e30f; bi[t] = 0; }
    float worst = 1e30f; int wslot = 0;

    for (int j = 0; j < NN; j++) {
        const float4* row = (const float4*)(sm + j * HH);
        float acc = 0.f;
        #pragma unroll
        for (int q = 0; q < HH / 4; q++) {
            float4 v = row[q];
            acc = fmaf(r[4 * q], v.x, acc);
            acc = fmaf(r[4 * q + 1], v.y, acc);
            acc = fmaf(r[4 * q + 2], v.z, acc);
            acc = fmaf(r[4 * q + 3], v.w, acc);
        }
        float dj = s + sq[j] - 2.f * acc;
        if (dj < worst && j != i) {
            #pragma unroll
            for (int t = 0; t < KK; t++) if (t == wslot) { bd[t] = dj; bi[t] = j; }
            float w = bd[0]; int ws = 0;
            #pragma unroll
            for (int t = 1; t < KK; t++) if (bd[t] > w) { w = bd[t]; ws = t; }
            worst = w; wslot = ws;
        }
    }
    #pragma unroll
    for (int t = 0; t < KK; t++) nbr[((size_t)b * NN + i) * KK + t] = bi[t];
}

// ---------------------------------------------------------------------------
// EdgeConv: CTA = 8 nodes of one graph, 256 threads.
// m @ W0 = h_i @ W0_top + (h_j - h_i) @ W0_bot; a_i precomputed.
// Two M=128,N=64,K=64 register-tiled GEMMs (8x4 acc/thread) + elu + k-sum.
// ---------------------------------------------------------------------------
#define EDGE_SMEM (23040 * 4)

__global__ __launch_bounds__(256, 2) void edge_kernel(
    const float* __restrict__ h, const int* __restrict__ nbr,
    const float* __restrict__ W0, const float* __restrict__ b0,
    const float* __restrict__ W1, const float* __restrict__ b1,
    float* __restrict__ out)
{
    extern __shared__ float sm[];
    float* sW0 = sm;            // 128*64 = 8192
    float* sW1 = sm + 8192;     // 64*64  = 4096
    float* sHi = sm + 12288;    // 8*64   = 512
    float* sA  = sm + 12800;    // 8*64   = 512
    float* sD  = sm + 13312;    // 128*68 = 8704  (pad 68, reused for E)
    float* sP  = sm + 22016;    // 2*8*64 = 1024

    int tid = threadIdx.x;
    int b = blockIdx.x >> 6;
    int node0 = (blockIdx.x & 63) * 8;

    {   // weights -> smem
        const float4* w04 = (const float4*)W0; float4* s04 = (float4*)sW0;
        for (int t = tid; t < 2048; t += 256) s04[t] = w04[t];
        const float4* w14 = (const float4*)W1; float4* s14 = (float4*)sW1;
        for (int t = tid; t < 1024; t += 256) s14[t] = w14[t];
    }
    for (int t = tid; t < 512; t += 256)
        sHi[t] = h[((size_t)b * NN + node0 + (t >> 6)) * HH + (t & 63)];
    __syncthreads();

    // a_i = h_i @ W0_top + b0  (8*64 outputs, 2 per thread)
    #pragma unroll
    for (int rr = 0; rr < 2; rr++) {
        int o = tid + 256 * rr; int na = o >> 6, f = o & 63;
        float acc = b0[f];
        #pragma unroll 8
        for (int d = 0; d < HH; d++) acc = fmaf(sHi[na * HH + d], sW0[d * HH + f], acc);
        sA[o] = acc;
    }
    {   // gather Dvec[m][d] = h_j - h_i  (2 threads per row, float4)
        int m = tid >> 1, half = tid & 1;
        int na = m >> 4, k = m & 15;
        int j = nbr[((size_t)b * NN + node0 + na) * KK + k];
        const float4* src = (const float4*)(h + ((size_t)b * NN + j) * HH) + half * 8;
        const float4* hi4 = (const float4*)(sHi + na * HH) + half * 8;
        float4* d4 = (float4*)(sD + m * 68) + half * 8;
        #pragma unroll
        for (int q = 0; q < 8; q++) {
            float4 v = src[q], u = hi4[q];
            d4[q] = make_float4(v.x - u.x, v.y - u.y, v.z - u.z, v.w - u.w);
        }
    }
    __syncthreads();

    int tm = tid >> 4, tn = tid & 15;
    int m0 = tm * 8;
    int na = tm >> 1;   // node for all 8 rows of this thread

    float acc[8][4];
    #pragma unroll
    for (int r = 0; r < 8; r++)
        { acc[r][0] = 0.f; acc[r][1] = 0.f; acc[r][2] = 0.f; acc[r][3] = 0.f; }

    // GEMM1: Dvec @ W0_bot
    #pragma unroll 4
    for (int d = 0; d < HH; d++) {
        float4 w = *(const float4*)(sW0 + (HH + d) * HH + tn * 4);
        #pragma unroll
        for (int r = 0; r < 8; r++) {
            float av = sD[(m0 + r) * 68 + d];
            acc[r][0] = fmaf(av, w.x, acc[r][0]);
            acc[r][1] = fmaf(av, w.y, acc[r][1]);
            acc[r][2] = fmaf(av, w.z, acc[r][2]);
            acc[r][3] = fmaf(av, w.w, acc[r][3]);
        }
    }
    __syncthreads();   // all Dvec reads done before overwriting with E

    float4 av4 = *(const float4*)(sA + na * 64 + tn * 4);
    #pragma unroll
    for (int r = 0; r < 8; r++) {
        float4 e;
        e.x = elu_f(acc[r][0] + av4.x);
        e.y = elu_f(acc[r][1] + av4.y);
        e.z = elu_f(acc[r][2] + av4.z);
        e.w = elu_f(acc[r][3] + av4.w);
        *(float4*)(sD + (m0 + r) * 68 + tn * 4) = e;
    }
    __syncthreads();

    // GEMM2: E @ W1
    #pragma unroll
    for (int r = 0; r < 8; r++)
        { acc[r][0] = 0.f; acc[r][1] = 0.f; acc[r][2] = 0.f; acc[r][3] = 0.f; }
    #pragma unroll 4
    for (int d = 0; d < HH; d++) {
        float4 w = *(const float4*)(sW1 + d * HH + tn * 4);
        #pragma unroll
        for (int r = 0; r < 8; r++) {
            float av = sD[(m0 + r) * 68 + d];
            acc[r][0] = fmaf(av, w.x, acc[r][0]);
            acc[r][1] = fmaf(av, w.y, acc[r][1]);
            acc[r][2] = fmaf(av, w.z, acc[r][2]);
            acc[r][3] = fmaf(av, w.w, acc[r][3]);
        }
    }
    // epilogue: bias + elu + partial sum over this thread's 8 k-rows
    {
        float4 bb = *(const float4*)(b1 + tn * 4);
        float s0 = 0.f, s1 = 0.f, s2 = 0.f, s3 = 0.f;
        #pragma unroll
        for (int r = 0; r < 8; r++) {
            s0 += elu_f(acc[r][0] + bb.x);
            s1 += elu_f(acc[r][1] + bb.y);
            s2 += elu_f(acc[r][2] + bb.z);
            s3 += elu_f(acc[r][3] + bb.w);
        }
        *(float4*)(sP + (tm & 1) * 512 + na * 64 + tn * 4) = make_float4(s0, s1, s2, s3);
    }
    __syncthreads();

    #pragma unroll
    for (int rr = 0; rr < 2; rr++) {
        int o = tid + 256 * rr;
        out[((size_t)b * NN + node0 + (o >> 6)) * HH + (o & 63)] = sP[o] + sP[512 + o];
    }
}

// ---------------------------------------------------------------------------
// Global max-pool + output MLP + log_softmax. One CTA (64 threads) per graph.
// ---------------------------------------------------------------------------
__global__ __launch_bounds__(64) void pool_kernel(
    const float* __restrict__ h,
    const float* __restrict__ W0, const float* __restrict__ b0,
    const float* __restrict__ W1, const float* __restrict__ b1,
    const float* __restrict__ W2, const float* __restrict__ b2,
    float* __restrict__ out)
{
    __shared__ float sW0[HH * HH], sW1[HH * HH], sW2[HH * 10];
    __shared__ float g0[HH], g1[HH], lg[10];

    int b = blockIdx.x, f = threadIdx.x;
    for (int t = f; t < HH * HH; t += 64) { sW0[t] = W0[t]; sW1[t] = W1[t]; }
    for (int t = f; t < HH * 10; t += 64) sW2[t] = W2[t];

    const float* hb = h + (size_t)b * NN * HH;
    float m0 = -1e30f, m1 = -1e30f, m2 = -1e30f, m3 = -1e30f;
    #pragma unroll 4
    for (int n = 0; n < NN; n += 4) {
        m0 = fmaxf(m0, hb[(n + 0) * HH + f]);
        m1 = fmaxf(m1, hb[(n + 1) * HH + f]);
        m2 = fmaxf(m2, hb[(n + 2) * HH + f]);
        m3 = fmaxf(m3, hb[(n + 3) * HH + f]);
    }
    g0[f] = fmaxf(fmaxf(m0, m1), fmaxf(m2, m3));
    __syncthreads();

    float acc = b0[f];
    #pragma unroll 8
    for (int d = 0; d < HH; d++) acc = fmaf(g0[d], sW0[d * HH + f], acc);
    g1[f] = elu_f(acc);
    __syncthreads();

    acc = b1[f];
    #pragma unroll 8
    for (int d = 0; d < HH; d++) acc = fmaf(g1[d], sW1[d * HH + f], acc);
    __syncthreads();
    g0[f] = elu_f(acc);
    __syncthreads();

    if (f < 10) {
        float a = b2[f];
        #pragma unroll 8
        for (int d = 0; d < HH; d++) a = fmaf(g0[d], sW2[d * 10 + f], a);
        lg[f] = a;
    }
    __syncthreads();

    if (f == 0) {
        float mx = lg[0];
        #pragma unroll
        for (int c = 1; c < 10; c++) mx = fmaxf(mx, lg[c]);
        float se = 0.f;
        #pragma unroll
        for (int c = 0; c < 10; c++) se += expf(lg[c] - mx);
        float lse = mx + logf(se);
        #pragma unroll
        for (int c = 0; c < 10; c++) out[b * 10 + c] = lg[c] - lse;
    }
}

// ---------------------------------------------------------------------------
extern "C" void kernel_launch(void* const* d_in, const int* in_sizes, int n_in,
                              void* d_out, int out_size)
{
    const float* x     = (const float*)d_in[0];
    const float* W_in0 = (const float*)d_in[1];
    const float* b_in0 = (const float*)d_in[2];
    const float* W_in1 = (const float*)d_in[3];
    const float* b_in1 = (const float*)d_in[4];
    const float* W_in2 = (const float*)d_in[5];
    const float* b_in2 = (const float*)d_in[6];
    const float* W_e0  = (const float*)d_in[7];
    const float* b_e0  = (const float*)d_in[8];
    const float* W_e1  = (const float*)d_in[9];
    const float* b_e1  = (const float*)d_in[10];
    const float* W_o0  = (const float*)d_in[11];
    const float* b_o0  = (const float*)d_in[12];
    const float* W_o1  = (const float*)d_in[13];
    const float* b_o1  = (const float*)d_in[14];
    const float* W_o2  = (const float*)d_in[15];
    const float* b_o2  = (const float*)d_in[16];

    void *pA, *pB, *pI;
    cudaGetSymbolAddress(&pA, g_hA);
    cudaGetSymbolAddress(&pB, g_hB);
    cudaGetSymbolAddress(&pI, g_idx);
    float* hA = (float*)pA;
    float* hB = (float*)pB;
    int*   nb = (int*)pI;

    cudaFuncSetAttribute(knn_kernel,  cudaFuncAttributeMaxDynamicSharedMemorySize, KNN_SMEM);
    cudaFuncSetAttribute(edge_kernel, cudaFuncAttributeMaxDynamicSharedMemorySize, EDGE_SMEM);

    input_kernel<<<BB * NN / 16, 256>>>(x, W_in0, b_in0, W_in1, b_in1, W_in2, b_in2, hA);

    for (int l = 0; l < 2; l++) {
        const float* src = l ? hB : hA;
        float*       dst = l ? hA : hB;
        knn_kernel<<<BB, 512, KNN_SMEM>>>(src, nb);
        edge_kernel<<<BB * NN / 8, 256, EDGE_SMEM>>>(
            src, nb,
            W_e0 + (size_t)l * 2 * HH * HH, b_e0 + (size_t)l * HH,
            W_e1 + (size_t)l * HH * HH,     b_e1 + (size_t)l * HH,
            dst);
    }

    pool_kernel<<<BB, 64>>>(hA, W_o0, b_o0, W_o1, b_o1, W_o2, b_o2, (float*)d_out);
}

// round 3
// speedup vs baseline: 1.2126x; 1.2126x over previous
#include <cuda_runtime.h>

#define BB 128
#define NN 512
#define FF 5
#define HH 64
#define KK 16

typedef unsigned long long u64;

// Scratch (device globals: allocation-free)
__device__ float g_hA[BB * NN * HH];   // 16 MB
__device__ float g_hB[BB * NN * HH];   // 16 MB
__device__ int   g_idx[BB * NN * KK];  // 4 MB

__device__ __forceinline__ float elu_f(float x) {
    return x > 0.f ? x : (__expf(x) - 1.f);
}

// ---- packed fp32x2 helpers (Blackwell FFMA2; exact fp32) ---------------
__device__ __forceinline__ u64 fma2_(u64 a, u64 b, u64 c) {
    u64 d;
    asm("fma.rn.f32x2 %0, %1, %2, %3;" : "=l"(d) : "l"(a), "l"(b), "l"(c));
    return d;
}
__device__ __forceinline__ u64 pack2_(float x) {
    u64 d;
    asm("mov.b64 %0, {%1, %1};" : "=l"(d) : "f"(x));
    return d;
}
__device__ __forceinline__ float2 unpack2_(u64 v) {
    float2 r;
    asm("mov.b64 {%0, %1}, %2;" : "=f"(r.x), "=f"(r.y) : "l"(v));
    return r;
}

// ---------------------------------------------------------------------------
// Input MLP: x[B,N,5] -> h[B,N,64], three elu layers.
// ---------------------------------------------------------------------------
__global__ __launch_bounds__(256) void input_kernel(
    const float* __restrict__ x,
    const float* __restrict__ W0, const float* __restrict__ b0,
    const float* __restrict__ W1, const float* __restrict__ b1,
    const float* __restrict__ W2, const float* __restrict__ b2,
    float* __restrict__ out)
{
    __shared__ float sW0[FF * HH];
    __shared__ float sW1[HH * HH];
    __shared__ float sW2[HH * HH];
    __shared__ float sx[16][FF];
    __shared__ float sh[16][HH];

    int tid = threadIdx.x;
    for (int t = tid; t < FF * HH; t += 256) sW0[t] = W0[t];
    for (int t = tid; t < HH * HH; t += 256) { sW1[t] = W1[t]; sW2[t] = W2[t]; }

    int node0 = blockIdx.x * 16;
    if (tid < 16 * FF) sx[tid / FF][tid % FF] = x[(size_t)(node0 + tid / FF) * FF + tid % FF];
    __syncthreads();

    int nl = tid >> 4, tn = tid & 15;

    float4 acc = *(const float4*)(b0 + tn * 4);
    #pragma unroll
    for (int d = 0; d < FF; d++) {
        float v = sx[nl][d];
        float4 w = *(const float4*)(sW0 + d * HH + tn * 4);
        acc.x = fmaf(v, w.x, acc.x); acc.y = fmaf(v, w.y, acc.y);
        acc.z = fmaf(v, w.z, acc.z); acc.w = fmaf(v, w.w, acc.w);
    }
    acc.x = elu_f(acc.x); acc.y = elu_f(acc.y); acc.z = elu_f(acc.z); acc.w = elu_f(acc.w);
    ((float4*)(sh[nl]))[tn] = acc;
    __syncthreads();

    float4 a2 = *(const float4*)(b1 + tn * 4);
    #pragma unroll 8
    for (int d = 0; d < HH; d++) {
        float v = sh[nl][d];
        float4 w = *(const float4*)(sW1 + d * HH + tn * 4);
        a2.x = fmaf(v, w.x, a2.x); a2.y = fmaf(v, w.y, a2.y);
        a2.z = fmaf(v, w.z, a2.z); a2.w = fmaf(v, w.w, a2.w);
    }
    __syncthreads();
    a2.x = elu_f(a2.x); a2.y = elu_f(a2.y); a2.z = elu_f(a2.z); a2.w = elu_f(a2.w);
    ((float4*)(sh[nl]))[tn] = a2;
    __syncthreads();

    float4 a3 = *(const float4*)(b2 + tn * 4);
    #pragma unroll 8
    for (int d = 0; d < HH; d++) {
        float v = sh[nl][d];
        float4 w = *(const float4*)(sW2 + d * HH + tn * 4);
        a3.x = fmaf(v, w.x, a3.x); a3.y = fmaf(v, w.y, a3.y);
        a3.z = fmaf(v, w.z, a3.z); a3.w = fmaf(v, w.w, a3.w);
    }
    a3.x = elu_f(a3.x); a3.y = elu_f(a3.y); a3.z = elu_f(a3.z); a3.w = elu_f(a3.w);
    *(float4*)(out + (size_t)(node0 + nl) * HH + tn * 4) = a3;
}

// ---------------------------------------------------------------------------
// kNN: one CTA per graph, h_b (512x64 fp32) in smem. f32x2 inner product:
// own row packed in 32 u64 regs; j rows arrive as packed pairs via LDS.128.
// j unrolled by 2 (two independent acc chains). Strict '<' replacement keeps
// earliest index (jax.lax.top_k tie behavior), j processed in ascending order.
// ---------------------------------------------------------------------------
#define KNN_SMEM ((NN * HH + NN) * 4)

#define TOPK_INSERT(DJ, J)                                                   \
    if ((DJ) < worst) {                                                      \
        _Pragma("unroll")                                                    \
        for (int t = 0; t < KK; t++) if (t == wslot) { bd[t] = (DJ); bi[t] = (J); } \
        float w_ = bd[0]; int ws_ = 0;                                       \
        _Pragma("unroll")                                                    \
        for (int t = 1; t < KK; t++) if (bd[t] > w_) { w_ = bd[t]; ws_ = t; } \
        worst = w_; wslot = ws_;                                             \
    }

__global__ __launch_bounds__(512, 1) void knn_kernel(
    const float* __restrict__ h, int* __restrict__ nbr)
{
    extern __shared__ float sm[];
    float* sq = sm + NN * HH;
    int b = blockIdx.x, i = threadIdx.x;

    const float4* src4 = (const float4*)(h + (size_t)b * NN * HH);
    float4* dst4 = (float4*)sm;
    for (int t = i; t < NN * HH / 4; t += NN) dst4[t] = src4[t];
    __syncthreads();

    // own row, packed as 32 f32x2 pairs
    u64 rp[HH / 2];
    const ulonglong2* myrow = (const ulonglong2*)(sm + i * HH);
    #pragma unroll
    for (int q = 0; q < HH / 4; q++) {
        ulonglong2 v = myrow[q];
        rp[2 * q] = v.x; rp[2 * q + 1] = v.y;
    }
    u64 s2 = 0ull;
    #pragma unroll
    for (int q = 0; q < HH / 2; q++) s2 = fma2_(rp[q], rp[q], s2);
    float2 sf = unpack2_(s2);
    float s = sf.x + sf.y;
    sq[i] = s;
    __syncthreads();

    float bd[KK]; int bi[KK];
    #pragma unroll
    for (int t = 0; t < KK; t++) { bd[t] = 1e30f; bi[t] = 0; }
    float worst = 1e30f; int wslot = 0;

    for (int j = 0; j < NN; j += 2) {
        const ulonglong2* r0 = (const ulonglong2*)(sm + j * HH);
        const ulonglong2* r1 = (const ulonglong2*)(sm + j * HH + HH);
        u64 a0 = 0ull, a1 = 0ull;
        #pragma unroll
        for (int q = 0; q < HH / 4; q++) {
            ulonglong2 v0 = r0[q];
            a0 = fma2_(rp[2 * q], v0.x, a0);
            a0 = fma2_(rp[2 * q + 1], v0.y, a0);
            ulonglong2 v1 = r1[q];
            a1 = fma2_(rp[2 * q], v1.x, a1);
            a1 = fma2_(rp[2 * q + 1], v1.y, a1);
        }
        float2 f0 = unpack2_(a0), f1 = unpack2_(a1);
        float dj0 = s + sq[j]     - 2.f * (f0.x + f0.y);
        float dj1 = s + sq[j + 1] - 2.f * (f1.x + f1.y);
        if (j == i)     dj0 = 1e30f;
        if (j + 1 == i) dj1 = 1e30f;
        TOPK_INSERT(dj0, j)
        TOPK_INSERT(dj1, j + 1)
    }
    #pragma unroll
    for (int t = 0; t < KK; t++) nbr[((size_t)b * NN + i) * KK + t] = bi[t];
}

// ---------------------------------------------------------------------------
// EdgeConv: CTA = 8 nodes, 256 threads. Two M=128,N=64,K=64 GEMMs via f32x2:
// W float4 is natively two packed pairs, av gets a 1-instr splat.
// ---------------------------------------------------------------------------
#define EDGE_SMEM (23040 * 4)

__global__ __launch_bounds__(256, 2) void edge_kernel(
    const float* __restrict__ h, const int* __restrict__ nbr,
    const float* __restrict__ W0, const float* __restrict__ b0,
    const float* __restrict__ W1, const float* __restrict__ b1,
    float* __restrict__ out)
{
    extern __shared__ float sm[];
    float* sW0 = sm;            // 128*64 = 8192
    float* sW1 = sm + 8192;     // 64*64  = 4096
    float* sHi = sm + 12288;    // 8*64   = 512
    float* sA  = sm + 12800;    // 8*64   = 512
    float* sD  = sm + 13312;    // 128*68 = 8704  (pad 68, reused for E)
    float* sP  = sm + 22016;    // 2*8*64 = 1024

    int tid = threadIdx.x;
    int b = blockIdx.x >> 6;
    int node0 = (blockIdx.x & 63) * 8;

    {
        const float4* w04 = (const float4*)W0; float4* s04 = (float4*)sW0;
        for (int t = tid; t < 2048; t += 256) s04[t] = w04[t];
        const float4* w14 = (const float4*)W1; float4* s14 = (float4*)sW1;
        for (int t = tid; t < 1024; t += 256) s14[t] = w14[t];
    }
    for (int t = tid; t < 512; t += 256)
        sHi[t] = h[((size_t)b * NN + node0 + (t >> 6)) * HH + (t & 63)];
    __syncthreads();

    // a_i = h_i @ W0_top + b0
    #pragma unroll
    for (int rr = 0; rr < 2; rr++) {
        int o = tid + 256 * rr; int na_ = o >> 6, f = o & 63;
        u64 acc2 = pack2_(0.f);
        const ulonglong2* hp = (const ulonglong2*)(sHi + na_ * HH);
        #pragma unroll 4
        for (int d = 0; d < HH; d += 2) {
            u64 hv = ((const u64*)hp)[d >> 1];
            float2 hvf = unpack2_(hv);
            u64 w2;
            asm("mov.b64 %0, {%1, %2};" : "=l"(w2)
                : "f"(sW0[d * HH + f]), "f"(sW0[(d + 1) * HH + f]));
            u64 h2;
            asm("mov.b64 %0, {%1, %2};" : "=l"(h2) : "f"(hvf.x), "f"(hvf.y));
            acc2 = fma2_(h2, w2, acc2);
        }
        float2 af = unpack2_(acc2);
        sA[o] = af.x + af.y + b0[f];
    }
    {   // gather Dvec[m][d] = h_j - h_i
        int m = tid >> 1, half = tid & 1;
        int na_ = m >> 4, k = m & 15;
        int j = nbr[((size_t)b * NN + node0 + na_) * KK + k];
        const float4* src = (const float4*)(h + ((size_t)b * NN + j) * HH) + half * 8;
        const float4* hi4 = (const float4*)(sHi + na_ * HH) + half * 8;
        float4* d4 = (float4*)(sD + m * 68) + half * 8;
        #pragma unroll
        for (int q = 0; q < 8; q++) {
            float4 v = src[q], u = hi4[q];
            d4[q] = make_float4(v.x - u.x, v.y - u.y, v.z - u.z, v.w - u.w);
        }
    }
    __syncthreads();

    int tm = tid >> 4, tn = tid & 15;
    int m0 = tm * 8;
    int na = tm >> 1;

    u64 acc[8][2];
    #pragma unroll
    for (int r = 0; r < 8; r++) { acc[r][0] = 0ull; acc[r][1] = 0ull; }

    // GEMM1: Dvec @ W0_bot  (f32x2, paired over N)
    #pragma unroll 4
    for (int d = 0; d < HH; d++) {
        ulonglong2 w2 = *(const ulonglong2*)(sW0 + (HH + d) * HH + tn * 4);
        #pragma unroll
        for (int r = 0; r < 8; r++) {
            u64 av2 = pack2_(sD[(m0 + r) * 68 + d]);
            acc[r][0] = fma2_(av2, w2.x, acc[r][0]);
            acc[r][1] = fma2_(av2, w2.y, acc[r][1]);
        }
    }
    __syncthreads();

    float4 av4 = *(const float4*)(sA + na * 64 + tn * 4);
    #pragma unroll
    for (int r = 0; r < 8; r++) {
        float2 p0 = unpack2_(acc[r][0]);
        float2 p1 = unpack2_(acc[r][1]);
        float4 e;
        e.x = elu_f(p0.x + av4.x);
        e.y = elu_f(p0.y + av4.y);
        e.z = elu_f(p1.x + av4.z);
        e.w = elu_f(p1.y + av4.w);
        *(float4*)(sD + (m0 + r) * 68 + tn * 4) = e;
    }
    __syncthreads();

    // GEMM2: E @ W1  (f32x2)
    #pragma unroll
    for (int r = 0; r < 8; r++) { acc[r][0] = 0ull; acc[r][1] = 0ull; }
    #pragma unroll 4
    for (int d = 0; d < HH; d++) {
        ulonglong2 w2 = *(const ulonglong2*)(sW1 + d * HH + tn * 4);
        #pragma unroll
        for (int r = 0; r < 8; r++) {
            u64 av2 = pack2_(sD[(m0 + r) * 68 + d]);
            acc[r][0] = fma2_(av2, w2.x, acc[r][0]);
            acc[r][1] = fma2_(av2, w2.y, acc[r][1]);
        }
    }
    {
        float4 bb = *(const float4*)(b1 + tn * 4);
        float s0 = 0.f, s1 = 0.f, s2 = 0.f, s3 = 0.f;
        #pragma unroll
        for (int r = 0; r < 8; r++) {
            float2 p0 = unpack2_(acc[r][0]);
            float2 p1 = unpack2_(acc[r][1]);
            s0 += elu_f(p0.x + bb.x);
            s1 += elu_f(p0.y + bb.y);
            s2 += elu_f(p1.x + bb.z);
            s3 += elu_f(p1.y + bb.w);
        }
        *(float4*)(sP + (tm & 1) * 512 + na * 64 + tn * 4) = make_float4(s0, s1, s2, s3);
    }
    __syncthreads();

    #pragma unroll
    for (int rr = 0; rr < 2; rr++) {
        int o = tid + 256 * rr;
        out[((size_t)b * NN + node0 + (o >> 6)) * HH + (o & 63)] = sP[o] + sP[512 + o];
    }
}

// ---------------------------------------------------------------------------
// Global max-pool + output MLP + log_softmax. One CTA (64 threads) per graph.
// ---------------------------------------------------------------------------
__global__ __launch_bounds__(64) void pool_kernel(
    const float* __restrict__ h,
    const float* __restrict__ W0, const float* __restrict__ b0,
    const float* __restrict__ W1, const float* __restrict__ b1,
    const float* __restrict__ W2, const float* __restrict__ b2,
    float* __restrict__ out)
{
    __shared__ float sW0[HH * HH], sW1[HH * HH], sW2[HH * 10];
    __shared__ float g0[HH], g1[HH], lg[10];

    int b = blockIdx.x, f = threadIdx.x;
    for (int t = f; t < HH * HH; t += 64) { sW0[t] = W0[t]; sW1[t] = W1[t]; }
    for (int t = f; t < HH * 10; t += 64) sW2[t] = W2[t];

    const float* hb = h + (size_t)b * NN * HH;
    float m0 = -1e30f, m1 = -1e30f, m2 = -1e30f, m3 = -1e30f;
    #pragma unroll 4
    for (int n = 0; n < NN; n += 4) {
        m0 = fmaxf(m0, hb[(n + 0) * HH + f]);
        m1 = fmaxf(m1, hb[(n + 1) * HH + f]);
        m2 = fmaxf(m2, hb[(n + 2) * HH + f]);
        m3 = fmaxf(m3, hb[(n + 3) * HH + f]);
    }
    g0[f] = fmaxf(fmaxf(m0, m1), fmaxf(m2, m3));
    __syncthreads();

    float acc = b0[f];
    #pragma unroll 8
    for (int d = 0; d < HH; d++) acc = fmaf(g0[d], sW0[d * HH + f], acc);
    g1[f] = elu_f(acc);
    __syncthreads();

    acc = b1[f];
    #pragma unroll 8
    for (int d = 0; d < HH; d++) acc = fmaf(g1[d], sW1[d * HH + f], acc);
    __syncthreads();
    g0[f] = elu_f(acc);
    __syncthreads();

    if (f < 10) {
        float a = b2[f];
        #pragma unroll 8
        for (int d = 0; d < HH; d++) a = fmaf(g0[d], sW2[d * 10 + f], a);
        lg[f] = a;
    }
    __syncthreads();

    if (f == 0) {
        float mx = lg[0];
        #pragma unroll
        for (int c = 1; c < 10; c++) mx = fmaxf(mx, lg[c]);
        float se = 0.f;
        #pragma unroll
        for (int c = 0; c < 10; c++) se += expf(lg[c] - mx);
        float lse = mx + logf(se);
        #pragma unroll
        for (int c = 0; c < 10; c++) out[b * 10 + c] = lg[c] - lse;
    }
}

// ---------------------------------------------------------------------------
extern "C" void kernel_launch(void* const* d_in, const int* in_sizes, int n_in,
                              void* d_out, int out_size)
{
    const float* x     = (const float*)d_in[0];
    const float* W_in0 = (const float*)d_in[1];
    const float* b_in0 = (const float*)d_in[2];
    const float* W_in1 = (const float*)d_in[3];
    const float* b_in1 = (const float*)d_in[4];
    const float* W_in2 = (const float*)d_in[5];
    const float* b_in2 = (const float*)d_in[6];
    const float* W_e0  = (const float*)d_in[7];
    const float* b_e0  = (const float*)d_in[8];
    const float* W_e1  = (const float*)d_in[9];
    const float* b_e1  = (const float*)d_in[10];
    const float* W_o0  = (const float*)d_in[11];
    const float* b_o0  = (const float*)d_in[12];
    const float* W_o1  = (const float*)d_in[13];
    const float* b_o1  = (const float*)d_in[14];
    const float* W_o2  = (const float*)d_in[15];
    const float* b_o2  = (const float*)d_in[16];

    void *pA, *pB, *pI;
    cudaGetSymbolAddress(&pA, g_hA);
    cudaGetSymbolAddress(&pB, g_hB);
    cudaGetSymbolAddress(&pI, g_idx);
    float* hA = (float*)pA;
    float* hB = (float*)pB;
    int*   nb = (int*)pI;

    cudaFuncSetAttribute(knn_kernel,  cudaFuncAttributeMaxDynamicSharedMemorySize, KNN_SMEM);
    cudaFuncSetAttribute(edge_kernel, cudaFuncAttributeMaxDynamicSharedMemorySize, EDGE_SMEM);

    input_kernel<<<BB * NN / 16, 256>>>(x, W_in0, b_in0, W_in1, b_in1, W_in2, b_in2, hA);

    for (int l = 0; l < 2; l++) {
        const float* src = l ? hB : hA;
        float*       dst = l ? hA : hB;
        knn_kernel<<<BB, 512, KNN_SMEM>>>(src, nb);
        edge_kernel<<<BB * NN / 8, 256, EDGE_SMEM>>>(
            src, nb,
            W_e0 + (size_t)l * 2 * HH * HH, b_e0 + (size_t)l * HH,
            W_e1 + (size_t)l * HH * HH,     b_e1 + (size_t)l * HH,
            dst);
    }

    pool_kernel<<<BB, 64>>>(hA, W_o0, b_o0, W_o1, b_o1, W_o2, b_o2, (float*)d_out);
}

// round 4
// speedup vs baseline: 1.2390x; 1.0218x over previous
#include <cuda_runtime.h>

#define BB 128
#define NN 512
#define FF 5
#define HH 64
#define KK 16

typedef unsigned long long u64;

// Scratch (device globals: allocation-free)
__device__ float g_hA[BB * NN * HH];   // 16 MB
__device__ float g_hB[BB * NN * HH];   // 16 MB
__device__ int   g_idx[BB * NN * KK];  // 4 MB

__device__ __forceinline__ float elu_f(float x) {
    return x > 0.f ? x : (__expf(x) - 1.f);
}

// ---- packed fp32x2 helpers (Blackwell FFMA2; exact fp32) ---------------
__device__ __forceinline__ u64 fma2_(u64 a, u64 b, u64 c) {
    u64 d;
    asm("fma.rn.f32x2 %0, %1, %2, %3;" : "=l"(d) : "l"(a), "l"(b), "l"(c));
    return d;
}
__device__ __forceinline__ u64 pack2_(float x) {
    u64 d;
    asm("mov.b64 %0, {%1, %1};" : "=l"(d) : "f"(x));
    return d;
}
__device__ __forceinline__ float2 unpack2_(u64 v) {
    float2 r;
    asm("mov.b64 {%0, %1}, %2;" : "=f"(r.x), "=f"(r.y) : "l"(v));
    return r;
}

// ---------------------------------------------------------------------------
// Input MLP: x[B,N,5] -> h[B,N,64], three elu layers.
// ---------------------------------------------------------------------------
__global__ __launch_bounds__(256) void input_kernel(
    const float* __restrict__ x,
    const float* __restrict__ W0, const float* __restrict__ b0,
    const float* __restrict__ W1, const float* __restrict__ b1,
    const float* __restrict__ W2, const float* __restrict__ b2,
    float* __restrict__ out)
{
    __shared__ float sW0[FF * HH];
    __shared__ float sW1[HH * HH];
    __shared__ float sW2[HH * HH];
    __shared__ float sx[16][FF];
    __shared__ float sh[16][HH];

    int tid = threadIdx.x;
    for (int t = tid; t < FF * HH; t += 256) sW0[t] = W0[t];
    for (int t = tid; t < HH * HH; t += 256) { sW1[t] = W1[t]; sW2[t] = W2[t]; }

    int node0 = blockIdx.x * 16;
    if (tid < 16 * FF) sx[tid / FF][tid % FF] = x[(size_t)(node0 + tid / FF) * FF + tid % FF];
    __syncthreads();

    int nl = tid >> 4, tn = tid & 15;

    float4 acc = *(const float4*)(b0 + tn * 4);
    #pragma unroll
    for (int d = 0; d < FF; d++) {
        float v = sx[nl][d];
        float4 w = *(const float4*)(sW0 + d * HH + tn * 4);
        acc.x = fmaf(v, w.x, acc.x); acc.y = fmaf(v, w.y, acc.y);
        acc.z = fmaf(v, w.z, acc.z); acc.w = fmaf(v, w.w, acc.w);
    }
    acc.x = elu_f(acc.x); acc.y = elu_f(acc.y); acc.z = elu_f(acc.z); acc.w = elu_f(acc.w);
    ((float4*)(sh[nl]))[tn] = acc;
    __syncthreads();

    float4 a2 = *(const float4*)(b1 + tn * 4);
    #pragma unroll 8
    for (int d = 0; d < HH; d++) {
        float v = sh[nl][d];
        float4 w = *(const float4*)(sW1 + d * HH + tn * 4);
        a2.x = fmaf(v, w.x, a2.x); a2.y = fmaf(v, w.y, a2.y);
        a2.z = fmaf(v, w.z, a2.z); a2.w = fmaf(v, w.w, a2.w);
    }
    __syncthreads();
    a2.x = elu_f(a2.x); a2.y = elu_f(a2.y); a2.z = elu_f(a2.z); a2.w = elu_f(a2.w);
    ((float4*)(sh[nl]))[tn] = a2;
    __syncthreads();

    float4 a3 = *(const float4*)(b2 + tn * 4);
    #pragma unroll 8
    for (int d = 0; d < HH; d++) {
        float v = sh[nl][d];
        float4 w = *(const float4*)(sW2 + d * HH + tn * 4);
        a3.x = fmaf(v, w.x, a3.x); a3.y = fmaf(v, w.y, a3.y);
        a3.z = fmaf(v, w.z, a3.z); a3.w = fmaf(v, w.w, a3.w);
    }
    a3.x = elu_f(a3.x); a3.y = elu_f(a3.y); a3.z = elu_f(a3.z); a3.w = elu_f(a3.w);
    *(float4*)(out + (size_t)(node0 + nl) * HH + tn * 4) = a3;
}

// ---------------------------------------------------------------------------
// kNN with candidate-queue top-k.
// Hot loop: distance via f32x2 + cheap predicated push of (d,j) to a per-lane
// smem stack. Expensive exact insert runs only in warp-synchronized drains.
// Exact: stale 'worst' admits a superset; drain re-checks with exact floats,
// strict '<' in ascending-j order == jax.lax.top_k tie behavior.
// ---------------------------------------------------------------------------
#define STK_CAP 8
#define STK_STRIDE 9   // u64 stride per lane (bank stagger)
#define KNN_SMEM ((NN * HH + NN) * 4 + NN * STK_STRIDE * 8)

#define TOPK_INSERT(DJ, J)                                                   \
    if ((DJ) < worst) {                                                      \
        _Pragma("unroll")                                                    \
        for (int t = 0; t < KK; t++) if (t == wslot) { bd[t] = (DJ); bi[t] = (J); } \
        float w_ = bd[0]; int ws_ = 0;                                       \
        _Pragma("unroll")                                                    \
        for (int t = 1; t < KK; t++) if (bd[t] > w_) { w_ = bd[t]; ws_ = t; } \
        worst = w_; wslot = ws_;                                             \
    }

__global__ __launch_bounds__(512, 1) void knn_kernel(
    const float* __restrict__ h, int* __restrict__ nbr)
{
    extern __shared__ float sm[];
    float* sq = sm + NN * HH;
    u64* stkbase = (u64*)(sm + NN * HH + NN);
    int b = blockIdx.x, i = threadIdx.x;
    u64* stk = stkbase + i * STK_STRIDE;

    const float4* src4 = (const float4*)(h + (size_t)b * NN * HH);
    float4* dst4 = (float4*)sm;
    for (int t = i; t < NN * HH / 4; t += NN) dst4[t] = src4[t];
    __syncthreads();

    // own row, packed as 32 f32x2 pairs
    u64 rp[HH / 2];
    const ulonglong2* myrow = (const ulonglong2*)(sm + i * HH);
    #pragma unroll
    for (int q = 0; q < HH / 4; q++) {
        ulonglong2 v = myrow[q];
        rp[2 * q] = v.x; rp[2 * q + 1] = v.y;
    }
    u64 s2 = 0ull;
    #pragma unroll
    for (int q = 0; q < HH / 2; q++) s2 = fma2_(rp[q], rp[q], s2);
    float2 sf = unpack2_(s2);
    float s = sf.x + sf.y;
    sq[i] = s;
    __syncthreads();

    float bd[KK]; int bi[KK];
    #pragma unroll
    for (int t = 0; t < KK; t++) { bd[t] = 1e30f; bi[t] = 0; }
    float worst = 1e30f; int wslot = 0;
    int cnt = 0;

    for (int j = 0; j < NN; j += 2) {
        const ulonglong2* r0 = (const ulonglong2*)(sm + j * HH);
        const ulonglong2* r1 = (const ulonglong2*)(sm + j * HH + HH);
        u64 a0 = 0ull, a1 = 0ull;
        #pragma unroll
        for (int q = 0; q < HH / 4; q++) {
            ulonglong2 v0 = r0[q];
            a0 = fma2_(rp[2 * q], v0.x, a0);
            a0 = fma2_(rp[2 * q + 1], v0.y, a0);
            ulonglong2 v1 = r1[q];
            a1 = fma2_(rp[2 * q], v1.x, a1);
            a1 = fma2_(rp[2 * q + 1], v1.y, a1);
        }
        float2 f0 = unpack2_(a0), f1 = unpack2_(a1);
        float dj0 = s + sq[j]     - 2.f * (f0.x + f0.y);
        float dj1 = s + sq[j + 1] - 2.f * (f1.x + f1.y);
        if (j == i)     dj0 = 1e30f;
        if (j + 1 == i) dj1 = 1e30f;

        // cheap predicated pushes (stale-threshold superset; exact check in drain)
        if (dj0 < worst) {
            stk[cnt] = ((u64)__float_as_uint(dj0) << 32) | (unsigned)j;
            cnt++;
        }
        if (dj1 < worst) {
            stk[cnt] = ((u64)__float_as_uint(dj1) << 32) | (unsigned)(j + 1);
            cnt++;
        }
        if (__any_sync(0xffffffffu, cnt >= STK_CAP - 1)) {
            #pragma unroll
            for (int t = 0; t < STK_CAP; t++) {
                if (t < cnt) {
                    u64 e = stk[t];
                    float dd = __uint_as_float((unsigned)(e >> 32));
                    int jj = (int)(e & 0xffffffffull);
                    TOPK_INSERT(dd, jj)
                }
            }
            cnt = 0;
        }
    }
    // final flush
    #pragma unroll
    for (int t = 0; t < STK_CAP; t++) {
        if (t < cnt) {
            u64 e = stk[t];
            float dd = __uint_as_float((unsigned)(e >> 32));
            int jj = (int)(e & 0xffffffffull);
            TOPK_INSERT(dd, jj)
        }
    }

    #pragma unroll
    for (int t = 0; t < KK; t++) nbr[((size_t)b * NN + i) * KK + t] = bi[t];
}

// ---------------------------------------------------------------------------
// EdgeConv: PERSISTENT kernel. 296 CTAs loop over all (b, node-group) items;
// weights+biases loaded to smem once. Inner GEMMs d-chunked by 4 with float4
// av loads (LSU relief) + f32x2 FMA.
// ---------------------------------------------------------------------------
#define EDGE_ITEMS (BB * (NN / 8))          // 8192
#define EDGE_SMEM  (23168 * 4)

__global__ __launch_bounds__(256, 2) void edge_kernel(
    const float* __restrict__ h, const int* __restrict__ nbr,
    const float* __restrict__ W0, const float* __restrict__ b0,
    const float* __restrict__ W1, const float* __restrict__ b1,
    float* __restrict__ out)
{
    extern __shared__ float sm[];
    float* sW0 = sm;            // 128*64 = 8192
    float* sW1 = sm + 8192;     // 64*64  = 4096
    float* sHi = sm + 12288;    // 8*64   = 512
    float* sA  = sm + 12800;    // 8*64   = 512
    float* sD  = sm + 13312;    // 128*68 = 8704  (pad 68, reused for E)
    float* sP  = sm + 22016;    // 2*8*64 = 1024
    float* sB0 = sm + 23040;    // 64
    float* sB1 = sm + 23104;    // 64

    int tid = threadIdx.x;

    {   // weights + biases -> smem ONCE
        const float4* w04 = (const float4*)W0; float4* s04 = (float4*)sW0;
        for (int t = tid; t < 2048; t += 256) s04[t] = w04[t];
        const float4* w14 = (const float4*)W1; float4* s14 = (float4*)sW1;
        for (int t = tid; t < 1024; t += 256) s14[t] = w14[t];
        if (tid < 64) { sB0[tid] = b0[tid]; sB1[tid] = b1[tid]; }
    }
    __syncthreads();

    int tm = tid >> 4, tn = tid & 15;
    int m0 = tm * 8;
    int na = tm >> 1;

    for (int item = blockIdx.x; item < EDGE_ITEMS; item += gridDim.x) {
        int b = item >> 6;
        int node0 = (item & 63) * 8;

        for (int t = tid; t < 512; t += 256)
            sHi[t] = h[((size_t)b * NN + node0 + (t >> 6)) * HH + (t & 63)];
        __syncthreads();

        // a_i = h_i @ W0_top + b0
        #pragma unroll
        for (int rr = 0; rr < 2; rr++) {
            int o = tid + 256 * rr; int na_ = o >> 6, f = o & 63;
            u64 acc2 = 0ull;
            #pragma unroll 4
            for (int d = 0; d < HH; d += 2) {
                u64 hv = ((const u64*)(sHi + na_ * HH))[d >> 1];
                u64 w2;
                asm("mov.b64 %0, {%1, %2};" : "=l"(w2)
                    : "f"(sW0[d * HH + f]), "f"(sW0[(d + 1) * HH + f]));
                acc2 = fma2_(hv, w2, acc2);
            }
            float2 af = unpack2_(acc2);
            sA[o] = af.x + af.y + sB0[f];
        }
        {   // gather Dvec[m][d] = h_j - h_i
            int m = tid >> 1, half = tid & 1;
            int na_ = m >> 4, k = m & 15;
            int j = nbr[((size_t)b * NN + node0 + na_) * KK + k];
            const float4* src = (const float4*)(h + ((size_t)b * NN + j) * HH) + half * 8;
            const float4* hi4 = (const float4*)(sHi + na_ * HH) + half * 8;
            float4* d4 = (float4*)(sD + m * 68) + half * 8;
            #pragma unroll
            for (int q = 0; q < 8; q++) {
                float4 v = src[q], u = hi4[q];
                d4[q] = make_float4(v.x - u.x, v.y - u.y, v.z - u.z, v.w - u.w);
            }
        }
        __syncthreads();

        u64 acc[8][2];
        #pragma unroll
        for (int r = 0; r < 8; r++) { acc[r][0] = 0ull; acc[r][1] = 0ull; }

        // GEMM1: Dvec @ W0_bot  (d-chunked, float4 av loads, f32x2 FMA)
        #pragma unroll 2
        for (int d0 = 0; d0 < HH; d0 += 4) {
            float4 av4[8];
            #pragma unroll
            for (int r = 0; r < 8; r++)
                av4[r] = *(const float4*)(sD + (m0 + r) * 68 + d0);
            #pragma unroll
            for (int dd = 0; dd < 4; dd++) {
                ulonglong2 w2 = *(const ulonglong2*)(sW0 + (HH + d0 + dd) * HH + tn * 4);
                #pragma unroll
                for (int r = 0; r < 8; r++) {
                    float a = (dd == 0) ? av4[r].x : (dd == 1) ? av4[r].y
                            : (dd == 2) ? av4[r].z : av4[r].w;
                    u64 av2 = pack2_(a);
                    acc[r][0] = fma2_(av2, w2.x, acc[r][0]);
                    acc[r][1] = fma2_(av2, w2.y, acc[r][1]);
                }
            }
        }
        __syncthreads();

        float4 av4b = *(const float4*)(sA + na * 64 + tn * 4);
        #pragma unroll
        for (int r = 0; r < 8; r++) {
            float2 p0 = unpack2_(acc[r][0]);
            float2 p1 = unpack2_(acc[r][1]);
            float4 e;
            e.x = elu_f(p0.x + av4b.x);
            e.y = elu_f(p0.y + av4b.y);
            e.z = elu_f(p1.x + av4b.z);
            e.w = elu_f(p1.y + av4b.w);
            *(float4*)(sD + (m0 + r) * 68 + tn * 4) = e;
        }
        __syncthreads();

        // GEMM2: E @ W1
        #pragma unroll
        for (int r = 0; r < 8; r++) { acc[r][0] = 0ull; acc[r][1] = 0ull; }
        #pragma unroll 2
        for (int d0 = 0; d0 < HH; d0 += 4) {
            float4 av4[8];
            #pragma unroll
            for (int r = 0; r < 8; r++)
                av4[r] = *(const float4*)(sD + (m0 + r) * 68 + d0);
            #pragma unroll
            for (int dd = 0; dd < 4; dd++) {
                ulonglong2 w2 = *(const ulonglong2*)(sW1 + (d0 + dd) * HH + tn * 4);
                #pragma unroll
                for (int r = 0; r < 8; r++) {
                    float a = (dd == 0) ? av4[r].x : (dd == 1) ? av4[r].y
                            : (dd == 2) ? av4[r].z : av4[r].w;
                    u64 av2 = pack2_(a);
                    acc[r][0] = fma2_(av2, w2.x, acc[r][0]);
                    acc[r][1] = fma2_(av2, w2.y, acc[r][1]);
                }
            }
        }
        {
            float4 bb = *(const float4*)(sB1 + tn * 4);
            float s0 = 0.f, s1 = 0.f, s2 = 0.f, s3 = 0.f;
            #pragma unroll
            for (int r = 0; r < 8; r++) {
                float2 p0 = unpack2_(acc[r][0]);
                float2 p1 = unpack2_(acc[r][1]);
                s0 += elu_f(p0.x + bb.x);
                s1 += elu_f(p0.y + bb.y);
                s2 += elu_f(p1.x + bb.z);
                s3 += elu_f(p1.y + bb.w);
            }
            *(float4*)(sP + (tm & 1) * 512 + na * 64 + tn * 4) = make_float4(s0, s1, s2, s3);
        }
        __syncthreads();

        #pragma unroll
        for (int rr = 0; rr < 2; rr++) {
            int o = tid + 256 * rr;
            out[((size_t)b * NN + node0 + (o >> 6)) * HH + (o & 63)] = sP[o] + sP[512 + o];
        }
        __syncthreads();
    }
}

// ---------------------------------------------------------------------------
// Global max-pool + output MLP + log_softmax. One CTA (64 threads) per graph.
// ---------------------------------------------------------------------------
__global__ __launch_bounds__(64) void pool_kernel(
    const float* __restrict__ h,
    const float* __restrict__ W0, const float* __restrict__ b0,
    const float* __restrict__ W1, const float* __restrict__ b1,
    const float* __restrict__ W2, const float* __restrict__ b2,
    float* __restrict__ out)
{
    __shared__ float sW0[HH * HH], sW1[HH * HH], sW2[HH * 10];
    __shared__ float g0[HH], g1[HH], lg[10];

    int b = blockIdx.x, f = threadIdx.x;
    for (int t = f; t < HH * HH; t += 64) { sW0[t] = W0[t]; sW1[t] = W1[t]; }
    for (int t = f; t < HH * 10; t += 64) sW2[t] = W2[t];

    const float* hb = h + (size_t)b * NN * HH;
    float m0 = -1e30f, m1 = -1e30f, m2 = -1e30f, m3 = -1e30f;
    #pragma unroll 4
    for (int n = 0; n < NN; n += 4) {
        m0 = fmaxf(m0, hb[(n + 0) * HH + f]);
        m1 = fmaxf(m1, hb[(n + 1) * HH + f]);
        m2 = fmaxf(m2, hb[(n + 2) * HH + f]);
        m3 = fmaxf(m3, hb[(n + 3) * HH + f]);
    }
    g0[f] = fmaxf(fmaxf(m0, m1), fmaxf(m2, m3));
    __syncthreads();

    float acc = b0[f];
    #pragma unroll 8
    for (int d = 0; d < HH; d++) acc = fmaf(g0[d], sW0[d * HH + f], acc);
    g1[f] = elu_f(acc);
    __syncthreads();

    acc = b1[f];
    #pragma unroll 8
    for (int d = 0; d < HH; d++) acc = fmaf(g1[d], sW1[d * HH + f], acc);
    __syncthreads();
    g0[f] = elu_f(acc);
    __syncthreads();

    if (f < 10) {
        float a = b2[f];
        #pragma unroll 8
        for (int d = 0; d < HH; d++) a = fmaf(g0[d], sW2[d * 10 + f], a);
        lg[f] = a;
    }
    __syncthreads();

    if (f == 0) {
        float mx = lg[0];
        #pragma unroll
        for (int c = 1; c < 10; c++) mx = fmaxf(mx, lg[c]);
        float se = 0.f;
        #pragma unroll
        for (int c = 0; c < 10; c++) se += expf(lg[c] - mx);
        float lse = mx + logf(se);
        #pragma unroll
        for (int c = 0; c < 10; c++) out[b * 10 + c] = lg[c] - lse;
    }
}

// ---------------------------------------------------------------------------
extern "C" void kernel_launch(void* const* d_in, const int* in_sizes, int n_in,
                              void* d_out, int out_size)
{
    const float* x     = (const float*)d_in[0];
    const float* W_in0 = (const float*)d_in[1];
    const float* b_in0 = (const float*)d_in[2];
    const float* W_in1 = (const float*)d_in[3];
    const float* b_in1 = (const float*)d_in[4];
    const float* W_in2 = (const float*)d_in[5];
    const float* b_in2 = (const float*)d_in[6];
    const float* W_e0  = (const float*)d_in[7];
    const float* b_e0  = (const float*)d_in[8];
    const float* W_e1  = (const float*)d_in[9];
    const float* b_e1  = (const float*)d_in[10];
    const float* W_o0  = (const float*)d_in[11];
    const float* b_o0  = (const float*)d_in[12];
    const float* W_o1  = (const float*)d_in[13];
    const float* b_o1  = (const float*)d_in[14];
    const float* W_o2  = (const float*)d_in[15];
    const float* b_o2  = (const float*)d_in[16];

    void *pA, *pB, *pI;
    cudaGetSymbolAddress(&pA, g_hA);
    cudaGetSymbolAddress(&pB, g_hB);
    cudaGetSymbolAddress(&pI, g_idx);
    float* hA = (float*)pA;
    float* hB = (float*)pB;
    int*   nb = (int*)pI;

    cudaFuncSetAttribute(knn_kernel,  cudaFuncAttributeMaxDynamicSharedMemorySize, KNN_SMEM);
    cudaFuncSetAttribute(edge_kernel, cudaFuncAttributeMaxDynamicSharedMemorySize, EDGE_SMEM);

    input_kernel<<<BB * NN / 16, 256>>>(x, W_in0, b_in0, W_in1, b_in1, W_in2, b_in2, hA);

    for (int l = 0; l < 2; l++) {
        const float* src = l ? hB : hA;
        float*       dst = l ? hA : hB;
        knn_kernel<<<BB, 512, KNN_SMEM>>>(src, nb);
        edge_kernel<<<296, 256, EDGE_SMEM>>>(
            src, nb,
            W_e0 + (size_t)l * 2 * HH * HH, b_e0 + (size_t)l * HH,
            W_e1 + (size_t)l * HH * HH,     b_e1 + (size_t)l * HH,
            dst);
    }

    pool_kernel<<<BB, 64>>>(hA, W_o0, b_o0, W_o1, b_o1, W_o2, b_o2, (float*)d_out);
}